// round 1
// baseline (speedup 1.0000x reference)
#include <cuda_runtime.h>
#include <cstdint>
#include <math_constants.h>

#define N_NODES 100000
#define E_EDGES 1600000
#define IN_F    128
#define OUT_F   32
#define HEADS   6
#define HC      (HEADS * OUT_F)   // 192
#define NEG_SLOPE 0.2f

// ---------------- scratch (device globals; no allocation allowed) ----------
__device__ float g_xp [N_NODES * HC];      // projected features [N,H,C]
__device__ float g_as [N_NODES * HEADS];   // per-node src logit half
__device__ float g_ad [N_NODES * HEADS];   // per-node dst logit half
__device__ float g_m  [N_NODES * HEADS];   // segment max
__device__ float g_s  [N_NODES * HEADS];   // segment sum
__device__ float g_acc[N_NODES * HC];      // aggregation accumulator [N,H,C]
__device__ float g_e  [E_EDGES * HEADS];   // per-edge logits / exp values
__device__ int   g_src[E_EDGES];
__device__ int   g_dst[E_EDGES];
__device__ int   g_is64;

// ---------------- helpers ---------------------------------------------------
__device__ __forceinline__ float atomicMaxF(float* addr, float val) {
    // sign-split trick: valid for all floats incl. -inf initial value
    if (val >= 0.0f)
        return __int_as_float(atomicMax((int*)addr, __float_as_int(val)));
    else
        return __uint_as_float(atomicMin((unsigned int*)addr, __float_as_uint(val)));
}

__device__ __forceinline__ void redAddF4(float4* addr, float4 v) {
    asm volatile("red.global.add.v4.f32 [%0], {%1, %2, %3, %4};"
                 :: "l"(addr), "f"(v.x), "f"(v.y), "f"(v.z), "f"(v.w)
                 : "memory");
}

__device__ __forceinline__ float selu_f(float x) {
    const float scale = 1.0507009873554805f;
    const float alpha = 1.6732632423543772f;
    return x > 0.0f ? scale * x : scale * alpha * (expf(x) - 1.0f);
}

// ---------------- kernels ---------------------------------------------------

// Detect whether edge_index is int64 or int32. Random int32 pairs read as
// int64 give values >= 2^32 (node ids < 1e5), so 16 consecutive in-range
// int64 reads => int64 layout.
__global__ void k_detect(const void* ei) {
    const long long* p = (const long long*)ei;
    int ok = 1;
    for (int i = 0; i < 16; i++) {
        long long v = p[i];
        if (v < 0 || v >= (long long)N_NODES) { ok = 0; break; }
    }
    g_is64 = ok;
}

__global__ void k_convert(const void* ei) {
    int i = blockIdx.x * blockDim.x + threadIdx.x;
    if (i >= E_EDGES) return;
    if (g_is64) {
        const long long* p = (const long long*)ei;
        g_src[i] = (int)p[i];
        g_dst[i] = (int)p[E_EDGES + i];
    } else {
        const int* p = (const int*)ei;
        g_src[i] = p[i];
        g_dst[i] = p[E_EDGES + i];
    }
}

// init: m = -inf, s = 0, acc = 0 (grid-stride)
__global__ void k_init() {
    int stride = gridDim.x * blockDim.x;
    for (int i = blockIdx.x * blockDim.x + threadIdx.x; i < N_NODES * HC; i += stride)
        g_acc[i] = 0.0f;
    for (int i = blockIdx.x * blockDim.x + threadIdx.x; i < N_NODES * HEADS; i += stride) {
        g_m[i] = -CUDART_INF_F;
        g_s[i] = 0.0f;
    }
}

// Projection: xp = x @ W (N x 128 @ 128 x 192), fused per-head attention
// logit halves. Block = 192 threads (6 warps = 6 heads), 8 rows per block.
#define PROJ_ROWS 8
__global__ void k_proj(const float* __restrict__ x, const float* __restrict__ W,
                       const float* __restrict__ att_src, const float* __restrict__ att_dst) {
    __shared__ float xs[PROJ_ROWS][IN_F];
    const int t    = threadIdx.x;          // 0..191
    const int row0 = blockIdx.x * PROJ_ROWS;

    for (int i = t; i < PROJ_ROWS * IN_F; i += HC) {
        int r = i / IN_F, c = i % IN_F;
        int row = row0 + r;
        xs[r][c] = (row < N_NODES) ? x[row * IN_F + c] : 0.0f;
    }
    __syncthreads();

    float acc[PROJ_ROWS];
#pragma unroll
    for (int r = 0; r < PROJ_ROWS; r++) acc[r] = 0.0f;

    for (int k = 0; k < IN_F; k++) {
        float w = W[k * HC + t];           // coalesced; L1-resident after warmup
#pragma unroll
        for (int r = 0; r < PROJ_ROWS; r++) acc[r] += xs[r][k] * w;
    }

    const int h = t >> 5, c = t & 31;      // warp == head, lane == channel
    const float aw_s = att_src[h * OUT_F + c];
    const float aw_d = att_dst[h * OUT_F + c];

#pragma unroll
    for (int r = 0; r < PROJ_ROWS; r++) {
        int row = row0 + r;
        if (row >= N_NODES) break;
        g_xp[row * HC + t] = acc[r];
        float vs = acc[r] * aw_s;
        float vd = acc[r] * aw_d;
#pragma unroll
        for (int off = 16; off > 0; off >>= 1) {
            vs += __shfl_down_sync(0xffffffffu, vs, off);
            vd += __shfl_down_sync(0xffffffffu, vd, off);
        }
        if (c == 0) {
            g_as[row * HEADS + h] = vs;
            g_ad[row * HEADS + h] = vd;
        }
    }
}

// Per-edge logits + LeakyReLU + segment max (atomic)
__global__ void k_edge_logit() {
    int i = blockIdx.x * blockDim.x + threadIdx.x;
    if (i >= E_EDGES) return;
    int s = g_src[i], d = g_dst[i];
#pragma unroll
    for (int h = 0; h < HEADS; h++) {
        float e = g_as[s * HEADS + h] + g_ad[d * HEADS + h];
        e = e > 0.0f ? e : NEG_SLOPE * e;
        g_e[i * HEADS + h] = e;
        atomicMaxF(&g_m[d * HEADS + h], e);
    }
}

// exp(e - m[dst]) + segment sum (atomic)
__global__ void k_edge_exp() {
    int i = blockIdx.x * blockDim.x + threadIdx.x;
    if (i >= E_EDGES) return;
    int d = g_dst[i];
#pragma unroll
    for (int h = 0; h < HEADS; h++) {
        float ex = __expf(g_e[i * HEADS + h] - g_m[d * HEADS + h]);
        g_e[i * HEADS + h] = ex;
        atomicAdd(&g_s[d * HEADS + h], ex);
    }
}

// Weighted scatter-aggregate: thread per (edge, head), 8x float4 vector RED
__global__ void k_aggregate() {
    int idx = blockIdx.x * blockDim.x + threadIdx.x;
    if (idx >= E_EDGES * HEADS) return;
    int e = idx / HEADS;
    int h = idx - e * HEADS;
    int d = g_dst[e];
    float alpha = g_e[idx] / (g_s[d * HEADS + h] + 1e-16f);
    int s = g_src[e];
    const float4* xp4  = (const float4*)&g_xp [s * HC + h * OUT_F];
    float4*       out4 = (float4*)      &g_acc[d * HC + h * OUT_F];
#pragma unroll
    for (int q = 0; q < 8; q++) {
        float4 v = xp4[q];
        v.x *= alpha; v.y *= alpha; v.z *= alpha; v.w *= alpha;
        redAddF4(&out4[q], v);
    }
}

// mean over heads + bias + SELU
__global__ void k_final(const float* __restrict__ bias, float* __restrict__ out) {
    int idx = blockIdx.x * blockDim.x + threadIdx.x;
    if (idx >= N_NODES * OUT_F) return;
    int n = idx >> 5;      // /32
    int c = idx & 31;
    float acc = 0.0f;
#pragma unroll
    for (int h = 0; h < HEADS; h++)
        acc += g_acc[n * HC + h * OUT_F + c];
    acc = acc * (1.0f / HEADS) + bias[c];
    out[idx] = selu_f(acc);
}

// ---------------- launch -----------------------------------------------------
extern "C" void kernel_launch(void* const* d_in, const int* in_sizes, int n_in,
                              void* d_out, int out_size) {
    const float* x        = (const float*)d_in[0];
    const void*  ei       = d_in[1];
    const float* W        = (const float*)d_in[2];
    const float* att_src  = (const float*)d_in[3];
    const float* att_dst  = (const float*)d_in[4];
    const float* bias     = (const float*)d_in[5];
    float*       out      = (float*)d_out;

    k_detect<<<1, 1>>>(ei);
    k_convert<<<(E_EDGES + 255) / 256, 256>>>(ei);
    k_init<<<592, 256>>>();  // 148 SMs * 4
    k_proj<<<(N_NODES + PROJ_ROWS - 1) / PROJ_ROWS, HC>>>(x, W, att_src, att_dst);
    k_edge_logit<<<(E_EDGES + 255) / 256, 256>>>();
    k_edge_exp<<<(E_EDGES + 255) / 256, 256>>>();
    k_aggregate<<<(E_EDGES * HEADS + 255) / 256, 256>>>();
    k_final<<<(N_NODES * OUT_F + 255) / 256, 256>>>(bias, out);
}

// round 3
// speedup vs baseline: 2.7560x; 2.7560x over previous
#include <cuda_runtime.h>
#include <cstdint>
#include <math_constants.h>

#define N_NODES 100000
#define E_EDGES 1600000
#define IN_F    128
#define OUT_F   32
#define HEADS   6
#define HC      (HEADS * OUT_F)   // 192
#define NEG_SLOPE 0.2f
#define SCAN_B  1024
#define NB      ((N_NODES + SCAN_B - 1) / SCAN_B)   // 98

// ---------------- scratch (device globals; no allocation allowed) ----------
__device__ float g_xp [N_NODES * HC];      // projected features [N,H,C]
__device__ float g_as [N_NODES * HEADS];   // per-node src logit half
__device__ float g_ad [N_NODES * HEADS];   // per-node dst logit half
__device__ int   g_src[E_EDGES];
__device__ int   g_dst[E_EDGES];
__device__ int   g_csr[E_EDGES];           // src ids grouped by dst
__device__ int   g_deg[N_NODES];
__device__ int   g_row[N_NODES];           // CSR row start (exclusive scan of deg)
__device__ int   g_cur[N_NODES];           // scatter cursors
__device__ int   g_scan[NB * SCAN_B];
__device__ int   g_bsum[NB];
__device__ int   g_boff[NB];
__device__ int   g_is64;

// ---------------- helpers ---------------------------------------------------
__device__ __forceinline__ float selu_f(float x) {
    const float scale = 1.0507009873554805f;
    const float alpha = 1.6732632423543772f;
    return x > 0.0f ? scale * x : scale * alpha * (expf(x) - 1.0f);
}

// ---------------- edge-index handling ---------------------------------------
__global__ void k_detect(const void* ei) {
    const long long* p = (const long long*)ei;
    int ok = 1;
    for (int i = 0; i < 16; i++) {
        long long v = p[i];
        if (v < 0 || v >= (long long)N_NODES) { ok = 0; break; }
    }
    g_is64 = ok;
}

__global__ void k_zero_deg() {
    int i = blockIdx.x * blockDim.x + threadIdx.x;
    if (i < N_NODES) g_deg[i] = 0;
}

// convert to int32 src/dst + degree histogram (by dst)
__global__ void k_convert_hist(const void* ei) {
    int i = blockIdx.x * blockDim.x + threadIdx.x;
    if (i >= E_EDGES) return;
    int s, d;
    if (g_is64) {
        const long long* p = (const long long*)ei;
        s = (int)p[i];
        d = (int)p[E_EDGES + i];
    } else {
        const int* p = (const int*)ei;
        s = p[i];
        d = p[E_EDGES + i];
    }
    g_src[i] = s;
    g_dst[i] = d;
    atomicAdd(&g_deg[d], 1);
}

// ---------------- exclusive scan of g_deg -> g_row ---------------------------
__global__ void k_scan1() {
    __shared__ int sh[SCAN_B];
    int t = threadIdx.x;
    int i = blockIdx.x * SCAN_B + t;
    int v = (i < N_NODES) ? g_deg[i] : 0;
    sh[t] = v;
    __syncthreads();
    for (int off = 1; off < SCAN_B; off <<= 1) {
        int add = (t >= off) ? sh[t - off] : 0;
        __syncthreads();
        sh[t] += add;
        __syncthreads();
    }
    g_scan[blockIdx.x * SCAN_B + t] = sh[t];
    if (t == SCAN_B - 1) g_bsum[blockIdx.x] = sh[t];
}

__global__ void k_scan2() {
    __shared__ int sh[128];
    int t = threadIdx.x;
    int v = (t < NB) ? g_bsum[t] : 0;
    sh[t] = v;
    __syncthreads();
    for (int off = 1; off < 128; off <<= 1) {
        int add = (t >= off) ? sh[t - off] : 0;
        __syncthreads();
        sh[t] += add;
        __syncthreads();
    }
    if (t < NB) g_boff[t] = sh[t] - v;   // exclusive
}

__global__ void k_scan3() {
    int i = blockIdx.x * blockDim.x + threadIdx.x;
    if (i >= N_NODES) return;
    int rs = g_scan[i] - g_deg[i] + g_boff[i / SCAN_B];   // exclusive scan
    g_row[i] = rs;
    g_cur[i] = rs;
}

__global__ void k_scatter() {
    int i = blockIdx.x * blockDim.x + threadIdx.x;
    if (i >= E_EDGES) return;
    int d = g_dst[i];
    int pos = atomicAdd(&g_cur[d], 1);
    g_csr[pos] = g_src[i];
}

// ---------------- projection GEMM (tiled, smem) ------------------------------
// Block: 256 threads, 32-row tile. Each thread computes 4 rows x 6 head-cols.
#define PR 32
__global__ __launch_bounds__(256) void k_proj(const float* __restrict__ x,
                                              const float* __restrict__ W,
                                              const float* __restrict__ att_src,
                                              const float* __restrict__ att_dst) {
    __shared__ float xs[PR][IN_F];       // 16 KB
    __shared__ float ws[32][HC];         // 24 KB
    const int t  = threadIdx.x;
    const int c  = t & 31;               // channel (lane)
    const int ry = t >> 5;               // row sub-index (warp id)
    const int row0 = blockIdx.x * PR;

    // load x tile (coalesced)
#pragma unroll
    for (int q = 0; q < (PR * IN_F) / 256; q++) {
        int i = t + 256 * q;
        int r = i >> 7, k = i & 127;
        xs[r][k] = x[(row0 + r) * IN_F + k];
    }

    float acc[4][6];
#pragma unroll
    for (int p = 0; p < 4; p++)
#pragma unroll
        for (int g = 0; g < 6; g++) acc[p][g] = 0.0f;

    float aS[6], aD[6];
#pragma unroll
    for (int g = 0; g < 6; g++) {
        aS[g] = att_src[g * OUT_F + c];
        aD[g] = att_dst[g * OUT_F + c];
    }

    for (int kc = 0; kc < 4; kc++) {
        const int k0 = kc * 32;
        __syncthreads();
        // load W k-chunk [32][192]
        for (int i = t; i < 32 * HC; i += 256) {
            int kk = i / HC, cc = i - kk * HC;
            ws[kk][cc] = W[(k0 + kk) * HC + cc];
        }
        __syncthreads();
#pragma unroll
        for (int kk = 0; kk < 32; kk++) {
            float xv[4], wv[6];
#pragma unroll
            for (int p = 0; p < 4; p++) xv[p] = xs[ry + 8 * p][k0 + kk];
#pragma unroll
            for (int g = 0; g < 6; g++) wv[g] = ws[kk][c + 32 * g];
#pragma unroll
            for (int p = 0; p < 4; p++)
#pragma unroll
                for (int g = 0; g < 6; g++) acc[p][g] += xv[p] * wv[g];
        }
    }

    // epilogue: store xp + warp-reduce attention halves
#pragma unroll
    for (int p = 0; p < 4; p++) {
        const int row = row0 + ry + 8 * p;
#pragma unroll
        for (int g = 0; g < 6; g++)
            g_xp[row * HC + g * OUT_F + c] = acc[p][g];
#pragma unroll
        for (int g = 0; g < 6; g++) {
            float vs = acc[p][g] * aS[g];
            float vd = acc[p][g] * aD[g];
#pragma unroll
            for (int off = 16; off > 0; off >>= 1) {
                vs += __shfl_down_sync(0xffffffffu, vs, off);
                vd += __shfl_down_sync(0xffffffffu, vd, off);
            }
            if (c == 0) {
                g_as[row * HEADS + g] = vs;
                g_ad[row * HEADS + g] = vd;
            }
        }
    }
}

// ---------------- fused softmax + aggregation + finalize ---------------------
// One warp per destination node. Single pass over its CSR edge list:
// per-head exp weights (no max subtraction needed: |logit| << 1 by construction),
// running denominator, weighted feature accumulation in registers, then
// head-mean + bias + SELU, one coalesced 128B store.
__global__ __launch_bounds__(256) void k_agg(const float* __restrict__ bias,
                                             float* __restrict__ out) {
    const int d    = (blockIdx.x * blockDim.x + threadIdx.x) >> 5;
    const int lane = threadIdx.x & 31;
    if (d >= N_NODES) return;

    const int base = g_row[d];
    const int deg  = g_deg[d];

    float ad_l = 0.0f;
    if (lane < HEADS) ad_l = g_ad[d * HEADS + lane];

    float a0 = 0, a1 = 0, a2 = 0, a3 = 0, a4 = 0, a5 = 0;
    float s = 0.0f;

    for (int j = 0; j < deg; j++) {
        const int src = g_csr[base + j];          // broadcast load
        float w = 0.0f;
        if (lane < HEADS) {
            float e = g_as[src * HEADS + lane] + ad_l;
            e = e > 0.0f ? e : NEG_SLOPE * e;
            w = __expf(e);
            s += w;
        }
        const float* __restrict__ xp = &g_xp[src * HC];
        const float w0 = __shfl_sync(0xffffffffu, w, 0);
        const float w1 = __shfl_sync(0xffffffffu, w, 1);
        const float w2 = __shfl_sync(0xffffffffu, w, 2);
        const float w3 = __shfl_sync(0xffffffffu, w, 3);
        const float w4 = __shfl_sync(0xffffffffu, w, 4);
        const float w5 = __shfl_sync(0xffffffffu, w, 5);
        a0 += w0 * xp[0 * OUT_F + lane];
        a1 += w1 * xp[1 * OUT_F + lane];
        a2 += w2 * xp[2 * OUT_F + lane];
        a3 += w3 * xp[3 * OUT_F + lane];
        a4 += w4 * xp[4 * OUT_F + lane];
        a5 += w5 * xp[5 * OUT_F + lane];
    }

    const float s0 = __shfl_sync(0xffffffffu, s, 0) + 1e-16f;
    const float s1 = __shfl_sync(0xffffffffu, s, 1) + 1e-16f;
    const float s2 = __shfl_sync(0xffffffffu, s, 2) + 1e-16f;
    const float s3 = __shfl_sync(0xffffffffu, s, 3) + 1e-16f;
    const float s4 = __shfl_sync(0xffffffffu, s, 4) + 1e-16f;
    const float s5 = __shfl_sync(0xffffffffu, s, 5) + 1e-16f;

    float o = a0 / s0 + a1 / s1 + a2 / s2 + a3 / s3 + a4 / s4 + a5 / s5;
    o = o * (1.0f / HEADS) + bias[lane];
    out[d * OUT_F + lane] = selu_f(o);
}

// ---------------- launch -----------------------------------------------------
extern "C" void kernel_launch(void* const* d_in, const int* in_sizes, int n_in,
                              void* d_out, int out_size) {
    const float* x       = (const float*)d_in[0];
    const void*  ei      = d_in[1];
    const float* W       = (const float*)d_in[2];
    const float* att_src = (const float*)d_in[3];
    const float* att_dst = (const float*)d_in[4];
    const float* bias    = (const float*)d_in[5];
    float*       out     = (float*)d_out;

    k_detect<<<1, 1>>>(ei);
    k_zero_deg<<<(N_NODES + 255) / 256, 256>>>();
    k_convert_hist<<<(E_EDGES + 255) / 256, 256>>>(ei);
    k_scan1<<<NB, SCAN_B>>>();
    k_scan2<<<1, 128>>>();
    k_scan3<<<(N_NODES + 255) / 256, 256>>>();
    k_scatter<<<(E_EDGES + 255) / 256, 256>>>();
    k_proj<<<N_NODES / PR, 256>>>(x, W, att_src, att_dst);
    k_agg<<<(N_NODES * 32 + 255) / 256, 256>>>(bias, out);
}

// round 6
// speedup vs baseline: 2.9500x; 1.0704x over previous
#include <cuda_runtime.h>
#include <cuda_fp16.h>
#include <cstdint>
#include <math_constants.h>

#define N_NODES 100000
#define E_EDGES 1600000
#define IN_F    128
#define OUT_F   32
#define HEADS   6
#define HC      (HEADS * OUT_F)   // 192
#define NEG_SLOPE 0.2f
#define SCAN_B  1024
#define NB      ((N_NODES + SCAN_B - 1) / SCAN_B)   // 98

// ---------------- scratch (device globals; no allocation allowed) ----------
__device__ __half g_xp_h[N_NODES * HC];    // projected features [N,H,C] (fp16; only agg reads)
__device__ float  g_as [N_NODES * HEADS];  // per-node src logit half
__device__ float  g_ad [N_NODES * HEADS];  // per-node dst logit half
__device__ int    g_src[E_EDGES];
__device__ int    g_dst[E_EDGES];
__device__ int    g_csr[E_EDGES];          // src ids grouped by dst
__device__ int    g_deg[N_NODES];
__device__ int    g_row[N_NODES];          // CSR row start
__device__ int    g_cur[N_NODES];          // scatter cursors
__device__ int    g_scan[NB * SCAN_B];
__device__ int    g_bsum[NB];
__device__ int    g_is64;

// ---------------- helpers ---------------------------------------------------
__device__ __forceinline__ float selu_f(float x) {
    const float scale = 1.0507009873554805f;
    const float alpha = 1.6732632423543772f;
    return x > 0.0f ? scale * x : scale * alpha * (expf(x) - 1.0f);
}

// ---------------- projection GEMM (tiled) + fused detect/zero ----------------
// 64-row tile, 256 threads, 8 rows per thread (one warp owns 8 rows).
// Also: block 0 thread 0 detects edge dtype; first blocks zero g_deg.
#define PR 64
#define KCH 16
__global__ __launch_bounds__(256) void k_proj(const float* __restrict__ x,
                                              const float* __restrict__ W,
                                              const float* __restrict__ att_src,
                                              const float* __restrict__ att_dst,
                                              const void* __restrict__ ei) {
    // --- fused edge-dtype detect + degree zeroing (cheap, before GEMM) ---
    if (blockIdx.x == 0 && threadIdx.x == 0) {
        const long long* p = (const long long*)ei;
        int ok = 1;
        for (int i = 0; i < 16; i++) {
            long long v = p[i];
            if (v < 0 || v >= (long long)N_NODES) { ok = 0; break; }
        }
        g_is64 = ok;
    }
    {
        int gid = blockIdx.x * 256 + threadIdx.x;
        if (gid < N_NODES) g_deg[gid] = 0;
    }

    __shared__ float xs[PR][IN_F];        // 32 KB
    __shared__ float ws[KCH][HC];         // 12 KB
    const int t    = threadIdx.x;
    const int c    = t & 31;              // lane = channel
    const int wy   = t >> 5;              // warp id = row group
    const int row0 = blockIdx.x * PR;

    // load x tile (coalesced, guarded)
#pragma unroll
    for (int q = 0; q < (PR * IN_F) / 256; q++) {
        int i = t + 256 * q;
        int r = i >> 7, k = i & 127;
        int row = row0 + r;
        xs[r][k] = (row < N_NODES) ? x[row * IN_F + k] : 0.0f;
    }

    float acc[8][6];
#pragma unroll
    for (int p = 0; p < 8; p++)
#pragma unroll
        for (int g = 0; g < 6; g++) acc[p][g] = 0.0f;

    float aS[6], aD[6];
#pragma unroll
    for (int g = 0; g < 6; g++) {
        aS[g] = att_src[g * OUT_F + c];
        aD[g] = att_dst[g * OUT_F + c];
    }

    for (int kc = 0; kc < IN_F / KCH; kc++) {
        const int k0 = kc * KCH;
        __syncthreads();
#pragma unroll
        for (int q = 0; q < (KCH * HC) / 256; q++) {
            int i = t + 256 * q;
            int kk = i / HC, cc = i - kk * HC;
            ws[kk][cc] = W[(k0 + kk) * HC + cc];
        }
        __syncthreads();
#pragma unroll
        for (int kk = 0; kk < KCH; kk++) {
            float xv[8], wv[6];
#pragma unroll
            for (int p = 0; p < 8; p++) xv[p] = xs[wy * 8 + p][k0 + kk];  // broadcast
#pragma unroll
            for (int g = 0; g < 6; g++) wv[g] = ws[kk][c + 32 * g];
#pragma unroll
            for (int p = 0; p < 8; p++)
#pragma unroll
                for (int g = 0; g < 6; g++) acc[p][g] += xv[p] * wv[g];
        }
    }

    // epilogue: fp16 xp store + warp-reduced attention halves
#pragma unroll
    for (int p = 0; p < 8; p++) {
        const int row = row0 + wy * 8 + p;
        if (row >= N_NODES) break;
#pragma unroll
        for (int g = 0; g < 6; g++)
            g_xp_h[row * HC + g * OUT_F + c] = __float2half(acc[p][g]);
#pragma unroll
        for (int g = 0; g < 6; g++) {
            float vs = acc[p][g] * aS[g];
            float vd = acc[p][g] * aD[g];
#pragma unroll
            for (int off = 16; off > 0; off >>= 1) {
                vs += __shfl_down_sync(0xffffffffu, vs, off);
                vd += __shfl_down_sync(0xffffffffu, vd, off);
            }
            if (c == 0) {
                g_as[row * HEADS + g] = vs;
                g_ad[row * HEADS + g] = vd;
            }
        }
    }
}

// ---------------- edge conversion + degree histogram -------------------------
__global__ void k_convert_hist(const void* __restrict__ ei) {
    int i = blockIdx.x * blockDim.x + threadIdx.x;
    if (i >= E_EDGES) return;
    int s, d;
    if (g_is64) {
        const long long* p = (const long long*)ei;
        s = (int)p[i];
        d = (int)p[E_EDGES + i];
    } else {
        const int* p = (const int*)ei;
        s = p[i];
        d = p[E_EDGES + i];
    }
    g_src[i] = s;
    g_dst[i] = d;
    atomicAdd(&g_deg[d], 1);
}

// ---------------- scan (block inclusive) -------------------------------------
__global__ void k_scan1() {
    __shared__ int sh[SCAN_B];
    int t = threadIdx.x;
    int i = blockIdx.x * SCAN_B + t;
    int v = (i < N_NODES) ? g_deg[i] : 0;
    sh[t] = v;
    __syncthreads();
    for (int off = 1; off < SCAN_B; off <<= 1) {
        int add = (t >= off) ? sh[t - off] : 0;
        __syncthreads();
        sh[t] += add;
        __syncthreads();
    }
    g_scan[blockIdx.x * SCAN_B + t] = sh[t];
    if (t == SCAN_B - 1) g_bsum[blockIdx.x] = sh[t];
}

// fused: per-block exclusive scan of bsum (redundant per block, cheap) + row/cur
__global__ void k_scan23() {
    __shared__ int sb[NB];
    int t = threadIdx.x;
    if (t < NB) sb[t] = g_bsum[t];
    __syncthreads();
    if (t == 0) {
        int run = 0;
        for (int b = 0; b < NB; b++) { int v = sb[b]; sb[b] = run; run += v; }
    }
    __syncthreads();
    int i = blockIdx.x * blockDim.x + t;
    if (i >= N_NODES) return;
    int rs = g_scan[i] - g_deg[i] + sb[i / SCAN_B];
    g_row[i] = rs;
    g_cur[i] = rs;
}

__global__ void k_scatter() {
    int i = blockIdx.x * blockDim.x + threadIdx.x;
    if (i >= E_EDGES) return;
    int d = g_dst[i];
    int pos = atomicAdd(&g_cur[d], 1);
    g_csr[pos] = g_src[i];
}

// ---------------- fused softmax + aggregation + finalize ---------------------
// One warp per dst. Cooperative CSR load (one coalesced load per 32 edges),
// 2-edge unroll for MLP, fp16 feature gathers, register accumulators.
__global__ __launch_bounds__(256) void k_agg(const float* __restrict__ bias,
                                             float* __restrict__ out) {
    const int d    = (blockIdx.x * blockDim.x + threadIdx.x) >> 5;
    const int lane = threadIdx.x & 31;
    if (d >= N_NODES) return;

    const int base = g_row[d];
    const int deg  = g_deg[d];

    float ad_l = 0.0f;
    if (lane < HEADS) ad_l = g_ad[d * HEADS + lane];

    float a0 = 0, a1 = 0, a2 = 0, a3 = 0, a4 = 0, a5 = 0;
    float s = 0.0f;

    for (int j0 = 0; j0 < deg; j0 += 32) {
        const int nv = min(32, deg - j0);
        int mysrc = 0;
        if (lane < nv) mysrc = g_csr[base + j0 + lane];

        int j = 0;
        for (; j + 1 < nv; j += 2) {
            const int sA = __shfl_sync(0xffffffffu, mysrc, j);
            const int sB = __shfl_sync(0xffffffffu, mysrc, j + 1);
            float wA = 0.0f, wB = 0.0f;
            if (lane < HEADS) {
                float eA = g_as[sA * HEADS + lane] + ad_l;
                float eB = g_as[sB * HEADS + lane] + ad_l;
                eA = eA > 0.0f ? eA : NEG_SLOPE * eA;
                eB = eB > 0.0f ? eB : NEG_SLOPE * eB;
                wA = __expf(eA);
                wB = __expf(eB);
                s += wA + wB;
            }
            const __half* __restrict__ xA = &g_xp_h[sA * HC];
            const __half* __restrict__ xB = &g_xp_h[sB * HC];
            const float wA0 = __shfl_sync(0xffffffffu, wA, 0);
            const float wA1 = __shfl_sync(0xffffffffu, wA, 1);
            const float wA2 = __shfl_sync(0xffffffffu, wA, 2);
            const float wA3 = __shfl_sync(0xffffffffu, wA, 3);
            const float wA4 = __shfl_sync(0xffffffffu, wA, 4);
            const float wA5 = __shfl_sync(0xffffffffu, wA, 5);
            const float wB0 = __shfl_sync(0xffffffffu, wB, 0);
            const float wB1 = __shfl_sync(0xffffffffu, wB, 1);
            const float wB2 = __shfl_sync(0xffffffffu, wB, 2);
            const float wB3 = __shfl_sync(0xffffffffu, wB, 3);
            const float wB4 = __shfl_sync(0xffffffffu, wB, 4);
            const float wB5 = __shfl_sync(0xffffffffu, wB, 5);
            a0 += wA0 * __half2float(xA[0 * OUT_F + lane]) + wB0 * __half2float(xB[0 * OUT_F + lane]);
            a1 += wA1 * __half2float(xA[1 * OUT_F + lane]) + wB1 * __half2float(xB[1 * OUT_F + lane]);
            a2 += wA2 * __half2float(xA[2 * OUT_F + lane]) + wB2 * __half2float(xB[2 * OUT_F + lane]);
            a3 += wA3 * __half2float(xA[3 * OUT_F + lane]) + wB3 * __half2float(xB[3 * OUT_F + lane]);
            a4 += wA4 * __half2float(xA[4 * OUT_F + lane]) + wB4 * __half2float(xB[4 * OUT_F + lane]);
            a5 += wA5 * __half2float(xA[5 * OUT_F + lane]) + wB5 * __half2float(xB[5 * OUT_F + lane]);
        }
        if (j < nv) {
            const int sA = __shfl_sync(0xffffffffu, mysrc, j);
            float wA = 0.0f;
            if (lane < HEADS) {
                float eA = g_as[sA * HEADS + lane] + ad_l;
                eA = eA > 0.0f ? eA : NEG_SLOPE * eA;
                wA = __expf(eA);
                s += wA;
            }
            const __half* __restrict__ xA = &g_xp_h[sA * HC];
            const float wA0 = __shfl_sync(0xffffffffu, wA, 0);
            const float wA1 = __shfl_sync(0xffffffffu, wA, 1);
            const float wA2 = __shfl_sync(0xffffffffu, wA, 2);
            const float wA3 = __shfl_sync(0xffffffffu, wA, 3);
            const float wA4 = __shfl_sync(0xffffffffu, wA, 4);
            const float wA5 = __shfl_sync(0xffffffffu, wA, 5);
            a0 += wA0 * __half2float(xA[0 * OUT_F + lane]);
            a1 += wA1 * __half2float(xA[1 * OUT_F + lane]);
            a2 += wA2 * __half2float(xA[2 * OUT_F + lane]);
            a3 += wA3 * __half2float(xA[3 * OUT_F + lane]);
            a4 += wA4 * __half2float(xA[4 * OUT_F + lane]);
            a5 += wA5 * __half2float(xA[5 * OUT_F + lane]);
        }
    }

    const float s0 = __shfl_sync(0xffffffffu, s, 0) + 1e-16f;
    const float s1 = __shfl_sync(0xffffffffu, s, 1) + 1e-16f;
    const float s2 = __shfl_sync(0xffffffffu, s, 2) + 1e-16f;
    const float s3 = __shfl_sync(0xffffffffu, s, 3) + 1e-16f;
    const float s4 = __shfl_sync(0xffffffffu, s, 4) + 1e-16f;
    const float s5 = __shfl_sync(0xffffffffu, s, 5) + 1e-16f;

    float o = a0 / s0 + a1 / s1 + a2 / s2 + a3 / s3 + a4 / s4 + a5 / s5;
    o = o * (1.0f / HEADS) + bias[lane];
    out[d * OUT_F + lane] = selu_f(o);
}

// ---------------- launch -----------------------------------------------------
extern "C" void kernel_launch(void* const* d_in, const int* in_sizes, int n_in,
                              void* d_out, int out_size) {
    const float* x       = (const float*)d_in[0];
    const void*  ei      = d_in[1];
    const float* W       = (const float*)d_in[2];
    const float* att_src = (const float*)d_in[3];
    const float* att_dst = (const float*)d_in[4];
    const float* bias    = (const float*)d_in[5];
    float*       out     = (float*)d_out;

    k_proj<<<(N_NODES + PR - 1) / PR, 256>>>(x, W, att_src, att_dst, ei);  // launch 0
    k_convert_hist<<<(E_EDGES + 255) / 256, 256>>>(ei);                    // launch 1
    k_scan1<<<NB, SCAN_B>>>();                                             // launch 2
    k_scan23<<<(N_NODES + 255) / 256, 256>>>();                            // launch 3
    k_scatter<<<(E_EDGES + 255) / 256, 256>>>();                           // launch 4
    k_agg<<<(N_NODES * 32 + 255) / 256, 256>>>(bias, out);                 // launch 5 (profiled)
}

// round 7
// speedup vs baseline: 4.6344x; 1.5710x over previous
#include <cuda_runtime.h>
#include <cuda_fp16.h>
#include <mma.h>
#include <cstdint>
#include <math_constants.h>

using namespace nvcuda;

#define N_NODES 100000
#define E_EDGES 1600000
#define IN_F    128
#define OUT_F   32
#define HEADS   6
#define HC      (HEADS * OUT_F)   // 192
#define NEG_SLOPE 0.2f
#define SCAN_B  1024
#define NB      ((N_NODES + SCAN_B - 1) / SCAN_B)   // 98

// ---------------- scratch (device globals; no allocation allowed) ----------
__device__ __half g_xp_h[N_NODES * HC];    // projected features [N,H,C] (fp16)
__device__ float  g_as [N_NODES * HEADS];
__device__ float  g_ad [N_NODES * HEADS];
__device__ int    g_src[E_EDGES];
__device__ int    g_dst[E_EDGES];
__device__ int    g_csr[E_EDGES];
__device__ int    g_deg[N_NODES];
__device__ int    g_row[N_NODES];
__device__ int    g_cur[N_NODES];
__device__ int    g_scan[NB * SCAN_B];
__device__ int    g_bsum[NB];
__device__ int    g_is64;

// ---------------- helpers ---------------------------------------------------
__device__ __forceinline__ float selu_f(float x) {
    const float scale = 1.0507009873554805f;
    const float alpha = 1.6732632423543772f;
    return x > 0.0f ? scale * x : scale * alpha * (expf(x) - 1.0f);
}

// ---------------- projection GEMM (tensor cores) + fused detect/zero ---------
// Block: 256 threads (8 warps), 64-row x 192-col tile.
// warp w: row-tile rt = w&3 (16 rows), col-half ch = w>>2 (96 cols = 6 frags).
#define PR 64
struct SmemGemm { __half xs[PR][136]; __half ws[32][200]; };
union SmemU { SmemGemm g; __half cs[PR][200]; };

__global__ __launch_bounds__(256) void k_proj(const float* __restrict__ x,
                                              const float* __restrict__ W,
                                              const float* __restrict__ att_src,
                                              const float* __restrict__ att_dst,
                                              const void* __restrict__ ei) {
    // fused edge-dtype detect + degree zeroing
    if (blockIdx.x == 0 && threadIdx.x == 0) {
        const long long* p = (const long long*)ei;
        int ok = 1;
        for (int i = 0; i < 16; i++) {
            long long v = p[i];
            if (v < 0 || v >= (long long)N_NODES) { ok = 0; break; }
        }
        g_is64 = ok;
    }
    {
        int gid = blockIdx.x * 256 + threadIdx.x;
        if (gid < N_NODES) g_deg[gid] = 0;
    }

    __shared__ SmemU su;
    const int t    = threadIdx.x;
    const int w    = t >> 5;
    const int lane = t & 31;
    const int rt   = w & 3;      // row tile (16 rows)
    const int ch   = w >> 2;     // col half (96 cols)
    const int row0 = blockIdx.x * PR;

    // load x tile -> fp16 smem (float2 -> half2), zero-pad OOB rows
#pragma unroll
    for (int q = 0; q < (PR * IN_F / 2) / 256; q++) {   // 16 iters
        int i  = t + 256 * q;
        int r  = i >> 6;            // 64 half2 per row
        int k2 = i & 63;
        int row = row0 + r;
        float2 f2 = (row < N_NODES) ? ((const float2*)x)[row * 64 + k2]
                                    : make_float2(0.0f, 0.0f);
        ((__half2*)&su.g.xs[r][0])[k2] = __floats2half2_rn(f2.x, f2.y);
    }

    wmma::fragment<wmma::accumulator, 16, 16, 16, float> acc[6];
#pragma unroll
    for (int j = 0; j < 6; j++) wmma::fill_fragment(acc[j], 0.0f);

    for (int kc = 0; kc < 4; kc++) {
        const int k0 = kc * 32;
        __syncthreads();
        // load W chunk [32][192] fp32 -> fp16 smem
#pragma unroll
        for (int q = 0; q < (32 * HC / 2) / 256; q++) {  // 12 iters
            int i  = t + 256 * q;
            int kk = i / 96;
            int c2 = i - kk * 96;
            float2 f2 = ((const float2*)W)[(k0 + kk) * 96 + c2];
            ((__half2*)&su.g.ws[kk][0])[c2] = __floats2half2_rn(f2.x, f2.y);
        }
        __syncthreads();
#pragma unroll
        for (int ks = 0; ks < 2; ks++) {
            wmma::fragment<wmma::matrix_a, 16, 16, 16, __half, wmma::row_major> af;
            wmma::load_matrix_sync(af, &su.g.xs[rt * 16][k0 + ks * 16], 136);
#pragma unroll
            for (int j = 0; j < 6; j++) {
                wmma::fragment<wmma::matrix_b, 16, 16, 16, __half, wmma::row_major> bf;
                wmma::load_matrix_sync(bf, &su.g.ws[ks * 16][ch * 96 + j * 16], 200);
                wmma::mma_sync(acc[j], af, bf, acc[j]);
            }
        }
    }

    // stage C to smem as fp16
    __syncthreads();
#pragma unroll
    for (int j = 0; j < 6; j++) {
        wmma::fragment<wmma::accumulator, 16, 16, 16, __half> hf;
#pragma unroll
        for (int i = 0; i < hf.num_elements; i++) hf.x[i] = __float2half(acc[j].x[i]);
        wmma::store_matrix_sync(&su.cs[rt * 16][ch * 96 + j * 16], hf, 200, wmma::mem_row_major);
    }
    __syncthreads();

    // xp copy to global (uint4 = 8 halfs), coalesced
#pragma unroll
    for (int q = 0; q < (PR * HC / 8) / 256; q++) {   // 6 iters
        int i  = t + 256 * q;
        int r  = i / 24;
        int q8 = i - r * 24;
        int row = row0 + r;
        if (row < N_NODES) {
            uint4 v = *(const uint4*)&su.cs[r][q8 * 8];
            ((uint4*)&g_xp_h[row * HC])[q8] = v;
        }
    }

    // attention halves: warp w handles rows w*8 .. w*8+7
    float aS[6], aD[6];
#pragma unroll
    for (int g = 0; g < 6; g++) {
        aS[g] = att_src[g * OUT_F + lane];
        aD[g] = att_dst[g * OUT_F + lane];
    }
#pragma unroll
    for (int p = 0; p < 8; p++) {
        const int ri  = w * 8 + p;
        const int row = row0 + ri;
        if (row >= N_NODES) break;
#pragma unroll
        for (int g = 0; g < 6; g++) {
            float v = __half2float(su.cs[ri][g * OUT_F + lane]);
            float vs = v * aS[g];
            float vd = v * aD[g];
#pragma unroll
            for (int off = 16; off > 0; off >>= 1) {
                vs += __shfl_down_sync(0xffffffffu, vs, off);
                vd += __shfl_down_sync(0xffffffffu, vd, off);
            }
            if (lane == 0) {
                g_as[row * HEADS + g] = vs;
                g_ad[row * HEADS + g] = vd;
            }
        }
    }
}

// ---------------- edge conversion + degree histogram -------------------------
__global__ void k_convert_hist(const void* __restrict__ ei) {
    int i = blockIdx.x * blockDim.x + threadIdx.x;
    if (i >= E_EDGES) return;
    int s, d;
    if (g_is64) {
        const long long* p = (const long long*)ei;
        s = (int)p[i];
        d = (int)p[E_EDGES + i];
    } else {
        const int* p = (const int*)ei;
        s = p[i];
        d = p[E_EDGES + i];
    }
    g_src[i] = s;
    g_dst[i] = d;
    atomicAdd(&g_deg[d], 1);
}

// ---------------- scan -------------------------------------------------------
__global__ void k_scan1() {
    __shared__ int sh[SCAN_B];
    int t = threadIdx.x;
    int i = blockIdx.x * SCAN_B + t;
    int v = (i < N_NODES) ? g_deg[i] : 0;
    sh[t] = v;
    __syncthreads();
    for (int off = 1; off < SCAN_B; off <<= 1) {
        int add = (t >= off) ? sh[t - off] : 0;
        __syncthreads();
        sh[t] += add;
        __syncthreads();
    }
    g_scan[blockIdx.x * SCAN_B + t] = sh[t];
    if (t == SCAN_B - 1) g_bsum[blockIdx.x] = sh[t];
}

__global__ void k_scan23() {
    __shared__ int sb[NB];
    int t = threadIdx.x;
    if (t < NB) sb[t] = g_bsum[t];
    __syncthreads();
    if (t == 0) {
        int run = 0;
        for (int b = 0; b < NB; b++) { int v = sb[b]; sb[b] = run; run += v; }
    }
    __syncthreads();
    int i = blockIdx.x * blockDim.x + t;
    if (i >= N_NODES) return;
    int rs = g_scan[i] - g_deg[i] + sb[i / SCAN_B];
    g_row[i] = rs;
    g_cur[i] = rs;
}

__global__ void k_scatter() {
    int i = blockIdx.x * blockDim.x + threadIdx.x;
    if (i >= E_EDGES) return;
    int d = g_dst[i];
    int pos = atomicAdd(&g_cur[d], 1);
    g_csr[pos] = g_src[i];
}

// ---------------- fused softmax + aggregation + finalize ---------------------
// One warp per dst. half2 lane remap: lanes 0-15 even heads / 16-31 odd heads,
// each lane covers channel pair (2*(l&15), +1). 3 half2 loads + 3 shfls per edge.
__global__ __launch_bounds__(256) void k_agg(const float* __restrict__ bias,
                                             float* __restrict__ out) {
    const int d    = (blockIdx.x * blockDim.x + threadIdx.x) >> 5;
    const int lane = threadIdx.x & 31;
    if (d >= N_NODES) return;

    const int base = g_row[d];
    const int deg  = g_deg[d];
    const int hsel = lane >> 4;          // 0: even heads, 1: odd heads

    float ad_l = 0.0f;
    if (lane < HEADS) ad_l = g_ad[d * HEADS + lane];

    float2 A0 = {0, 0}, A1 = {0, 0}, A2 = {0, 0};
    float s = 0.0f;

    for (int j0 = 0; j0 < deg; j0 += 32) {
        const int nv = min(32, deg - j0);
        int mysrc = 0;
        if (lane < nv) mysrc = g_csr[base + j0 + lane];

        int j = 0;
        for (; j + 1 < nv; j += 2) {
            const int sA = __shfl_sync(0xffffffffu, mysrc, j);
            const int sB = __shfl_sync(0xffffffffu, mysrc, j + 1);
            float wA = 0.0f, wB = 0.0f;
            if (lane < HEADS) {
                float eA = g_as[sA * HEADS + lane] + ad_l;
                float eB = g_as[sB * HEADS + lane] + ad_l;
                eA = eA > 0.0f ? eA : NEG_SLOPE * eA;
                eB = eB > 0.0f ? eB : NEG_SLOPE * eB;
                wA = __expf(eA);
                wB = __expf(eB);
                s += wA + wB;
            }
            const float wA0 = __shfl_sync(0xffffffffu, wA, 0 + hsel);
            const float wA1 = __shfl_sync(0xffffffffu, wA, 2 + hsel);
            const float wA2 = __shfl_sync(0xffffffffu, wA, 4 + hsel);
            const float wB0 = __shfl_sync(0xffffffffu, wB, 0 + hsel);
            const float wB1 = __shfl_sync(0xffffffffu, wB, 2 + hsel);
            const float wB2 = __shfl_sync(0xffffffffu, wB, 4 + hsel);
            const __half2* xA = (const __half2*)&g_xp_h[sA * HC];
            const __half2* xB = (const __half2*)&g_xp_h[sB * HC];
            float2 fA0 = __half22float2(xA[lane]);
            float2 fA1 = __half22float2(xA[32 + lane]);
            float2 fA2 = __half22float2(xA[64 + lane]);
            float2 fB0 = __half22float2(xB[lane]);
            float2 fB1 = __half22float2(xB[32 + lane]);
            float2 fB2 = __half22float2(xB[64 + lane]);
            A0.x += wA0 * fA0.x + wB0 * fB0.x;  A0.y += wA0 * fA0.y + wB0 * fB0.y;
            A1.x += wA1 * fA1.x + wB1 * fB1.x;  A1.y += wA1 * fA1.y + wB1 * fB1.y;
            A2.x += wA2 * fA2.x + wB2 * fB2.x;  A2.y += wA2 * fA2.y + wB2 * fB2.y;
        }
        if (j < nv) {
            const int sA = __shfl_sync(0xffffffffu, mysrc, j);
            float wA = 0.0f;
            if (lane < HEADS) {
                float eA = g_as[sA * HEADS + lane] + ad_l;
                eA = eA > 0.0f ? eA : NEG_SLOPE * eA;
                wA = __expf(eA);
                s += wA;
            }
            const float wA0 = __shfl_sync(0xffffffffu, wA, 0 + hsel);
            const float wA1 = __shfl_sync(0xffffffffu, wA, 2 + hsel);
            const float wA2 = __shfl_sync(0xffffffffu, wA, 4 + hsel);
            const __half2* xA = (const __half2*)&g_xp_h[sA * HC];
            float2 fA0 = __half22float2(xA[lane]);
            float2 fA1 = __half22float2(xA[32 + lane]);
            float2 fA2 = __half22float2(xA[64 + lane]);
            A0.x += wA0 * fA0.x;  A0.y += wA0 * fA0.y;
            A1.x += wA1 * fA1.x;  A1.y += wA1 * fA1.y;
            A2.x += wA2 * fA2.x;  A2.y += wA2 * fA2.y;
        }
    }

    // softmax denominators for this lane's 3 heads
    const float s0 = __shfl_sync(0xffffffffu, s, 0 + hsel) + 1e-16f;
    const float s1 = __shfl_sync(0xffffffffu, s, 2 + hsel) + 1e-16f;
    const float s2 = __shfl_sync(0xffffffffu, s, 4 + hsel) + 1e-16f;

    float ox = A0.x / s0 + A1.x / s1 + A2.x / s2;
    float oy = A0.y / s0 + A1.y / s1 + A2.y / s2;
    // combine even/odd head halves: lanes l and l^16 hold the same channel pair
    ox += __shfl_xor_sync(0xffffffffu, ox, 16);
    oy += __shfl_xor_sync(0xffffffffu, oy, 16);

    if (lane < 16) {
        const int c0 = 2 * lane;
        float2 r;
        r.x = selu_f(ox * (1.0f / HEADS) + bias[c0]);
        r.y = selu_f(oy * (1.0f / HEADS) + bias[c0 + 1]);
        ((float2*)&out[d * OUT_F])[lane] = r;
    }
}

// ---------------- launch -----------------------------------------------------
extern "C" void kernel_launch(void* const* d_in, const int* in_sizes, int n_in,
                              void* d_out, int out_size) {
    const float* x       = (const float*)d_in[0];
    const void*  ei      = d_in[1];
    const float* W       = (const float*)d_in[2];
    const float* att_src = (const float*)d_in[3];
    const float* att_dst = (const float*)d_in[4];
    const float* bias    = (const float*)d_in[5];
    float*       out     = (float*)d_out;

    k_proj<<<(N_NODES + PR - 1) / PR, 256>>>(x, W, att_src, att_dst, ei);  // 0
    k_convert_hist<<<(E_EDGES + 255) / 256, 256>>>(ei);                    // 1
    k_scan1<<<NB, SCAN_B>>>();                                             // 2
    k_scan23<<<(N_NODES + 255) / 256, 256>>>();                            // 3
    k_scatter<<<(E_EDGES + 255) / 256, 256>>>();                           // 4
    k_agg<<<(N_NODES * 32 + 255) / 256, 256>>>(bias, out);                 // 5 (profiled)
}

// round 10
// speedup vs baseline: 4.8109x; 1.0381x over previous
#include <cuda_runtime.h>
#include <cuda_fp16.h>
#include <mma.h>
#include <cstdint>
#include <math_constants.h>

using namespace nvcuda;

#define N_NODES 100000
#define E_EDGES 1600000
#define IN_F    128
#define OUT_F   32
#define HEADS   6
#define HC      (HEADS * OUT_F)   // 192
#define NEG_SLOPE 0.2f
#define SCAN_B  1024
#define NB      ((N_NODES + SCAN_B - 1) / SCAN_B)   // 98

// ---------------- scratch (device globals; no allocation allowed) ----------
__device__ __half g_xp_h[N_NODES * HC];    // projected features [N,H,C] (fp16)
__device__ float  g_as [N_NODES * HEADS];
__device__ float  g_ad [N_NODES * HEADS];
__device__ int    g_src[E_EDGES];
__device__ int    g_dst[E_EDGES];
__device__ int    g_csr[E_EDGES];
__device__ int    g_deg[N_NODES];
__device__ int    g_row[N_NODES];
__device__ int    g_cur[N_NODES];
__device__ int    g_scan[NB * SCAN_B];
__device__ int    g_bsum[NB];
__device__ int    g_is64;

// ---------------- helpers ---------------------------------------------------
__device__ __forceinline__ float selu_f(float x) {
    const float scale = 1.0507009873554805f;
    const float alpha = 1.6732632423543772f;
    return x > 0.0f ? scale * x : scale * alpha * (expf(x) - 1.0f);
}

// ---------------- edge-stream prep: detect dtype + zero degrees --------------
__global__ void k_prep(const void* __restrict__ ei) {
    if (blockIdx.x == 0 && threadIdx.x == 0) {
        const long long* p = (const long long*)ei;
        int ok = 1;
        for (int i = 0; i < 16; i++) {
            long long v = p[i];
            if (v < 0 || v >= (long long)N_NODES) { ok = 0; break; }
        }
        g_is64 = ok;
    }
    int gid = blockIdx.x * blockDim.x + threadIdx.x;
    if (gid < N_NODES) g_deg[gid] = 0;
}

// ---------------- projection GEMM (tensor cores) -----------------------------
// Block: 256 threads (8 warps), 64-row x 192-col tile.
#define PR 64
struct SmemGemm { __half xs[PR][136]; __half ws[32][200]; };
union SmemU { SmemGemm g; __half cs[PR][200]; };

__global__ __launch_bounds__(256) void k_proj(const float* __restrict__ x,
                                              const float* __restrict__ W,
                                              const float* __restrict__ att_src,
                                              const float* __restrict__ att_dst) {
    __shared__ SmemU su;
    const int t    = threadIdx.x;
    const int w    = t >> 5;
    const int lane = t & 31;
    const int rt   = w & 3;      // row tile (16 rows)
    const int ch   = w >> 2;     // col half (96 cols)
    const int row0 = blockIdx.x * PR;

    // load x tile -> fp16 smem (float2 -> half2), zero-pad OOB rows
#pragma unroll
    for (int q = 0; q < (PR * IN_F / 2) / 256; q++) {   // 16 iters
        int i  = t + 256 * q;
        int r  = i >> 6;            // 64 half2 per row
        int k2 = i & 63;
        int row = row0 + r;
        float2 f2 = (row < N_NODES) ? ((const float2*)x)[row * 64 + k2]
                                    : make_float2(0.0f, 0.0f);
        ((__half2*)&su.g.xs[r][0])[k2] = __floats2half2_rn(f2.x, f2.y);
    }

    wmma::fragment<wmma::accumulator, 16, 16, 16, float> acc[6];
#pragma unroll
    for (int j = 0; j < 6; j++) wmma::fill_fragment(acc[j], 0.0f);

    for (int kc = 0; kc < 4; kc++) {
        const int k0 = kc * 32;
        __syncthreads();
#pragma unroll
        for (int q = 0; q < (32 * HC / 2) / 256; q++) {  // 12 iters
            int i  = t + 256 * q;
            int kk = i / 96;
            int c2 = i - kk * 96;
            float2 f2 = ((const float2*)W)[(k0 + kk) * 96 + c2];
            ((__half2*)&su.g.ws[kk][0])[c2] = __floats2half2_rn(f2.x, f2.y);
        }
        __syncthreads();
#pragma unroll
        for (int ks = 0; ks < 2; ks++) {
            wmma::fragment<wmma::matrix_a, 16, 16, 16, __half, wmma::row_major> af;
            wmma::load_matrix_sync(af, &su.g.xs[rt * 16][k0 + ks * 16], 136);
#pragma unroll
            for (int j = 0; j < 6; j++) {
                wmma::fragment<wmma::matrix_b, 16, 16, 16, __half, wmma::row_major> bf;
                wmma::load_matrix_sync(bf, &su.g.ws[ks * 16][ch * 96 + j * 16], 200);
                wmma::mma_sync(acc[j], af, bf, acc[j]);
            }
        }
    }

    // stage C to smem as fp16
    __syncthreads();
#pragma unroll
    for (int j = 0; j < 6; j++) {
        wmma::fragment<wmma::accumulator, 16, 16, 16, __half> hf;
#pragma unroll
        for (int i = 0; i < hf.num_elements; i++) hf.x[i] = __float2half(acc[j].x[i]);
        wmma::store_matrix_sync(&su.cs[rt * 16][ch * 96 + j * 16], hf, 200, wmma::mem_row_major);
    }
    __syncthreads();

    // xp copy to global (uint4 = 8 halfs), coalesced
#pragma unroll
    for (int q = 0; q < (PR * HC / 8) / 256; q++) {   // 6 iters
        int i  = t + 256 * q;
        int r  = i / 24;
        int q8 = i - r * 24;
        int row = row0 + r;
        if (row < N_NODES) {
            uint4 v = *(const uint4*)&su.cs[r][q8 * 8];
            ((uint4*)&g_xp_h[row * HC])[q8] = v;
        }
    }

    // attention halves: warp w handles rows w*8 .. w*8+7
    float aS[6], aD[6];
#pragma unroll
    for (int g = 0; g < 6; g++) {
        aS[g] = att_src[g * OUT_F + lane];
        aD[g] = att_dst[g * OUT_F + lane];
    }
#pragma unroll
    for (int p = 0; p < 8; p++) {
        const int ri  = w * 8 + p;
        const int row = row0 + ri;
        if (row >= N_NODES) break;
#pragma unroll
        for (int g = 0; g < 6; g++) {
            float v = __half2float(su.cs[ri][g * OUT_F + lane]);
            float vs = v * aS[g];
            float vd = v * aD[g];
#pragma unroll
            for (int off = 16; off > 0; off >>= 1) {
                vs += __shfl_down_sync(0xffffffffu, vs, off);
                vd += __shfl_down_sync(0xffffffffu, vd, off);
            }
            if (lane == 0) {
                g_as[row * HEADS + g] = vs;
                g_ad[row * HEADS + g] = vd;
            }
        }
    }
}

// ---------------- edge conversion + degree histogram -------------------------
__global__ void k_convert_hist(const void* __restrict__ ei) {
    int i = blockIdx.x * blockDim.x + threadIdx.x;
    if (i >= E_EDGES) return;
    int s, d;
    if (g_is64) {
        const long long* p = (const long long*)ei;
        s = (int)p[i];
        d = (int)p[E_EDGES + i];
    } else {
        const int* p = (const int*)ei;
        s = p[i];
        d = p[E_EDGES + i];
    }
    g_src[i] = s;
    g_dst[i] = d;
    atomicAdd(&g_deg[d], 1);
}

// ---------------- scan (warp-shuffle version) --------------------------------
__global__ void k_scan1() {
    __shared__ int wsum[32];
    const int t = threadIdx.x, lane = t & 31, wid = t >> 5;
    const int i = blockIdx.x * SCAN_B + t;
    int v = (i < N_NODES) ? g_deg[i] : 0;
    int xv = v;
#pragma unroll
    for (int off = 1; off < 32; off <<= 1) {
        int y = __shfl_up_sync(0xffffffffu, xv, off);
        if (lane >= off) xv += y;
    }
    if (lane == 31) wsum[wid] = xv;
    __syncthreads();
    if (wid == 0) {
        int wv = wsum[lane];
#pragma unroll
        for (int off = 1; off < 32; off <<= 1) {
            int y = __shfl_up_sync(0xffffffffu, wv, off);
            if (lane >= off) wv += y;
        }
        wsum[lane] = wv;
    }
    __syncthreads();
    int incl = xv + (wid > 0 ? wsum[wid - 1] : 0);
    g_scan[blockIdx.x * SCAN_B + t] = incl;
    if (t == SCAN_B - 1) g_bsum[blockIdx.x] = incl;
}

__global__ void k_scan23() {
    __shared__ int sb[NB];
    int t = threadIdx.x;
    if (t < NB) sb[t] = g_bsum[t];
    __syncthreads();
    if (t == 0) {
        int run = 0;
        for (int b = 0; b < NB; b++) { int v = sb[b]; sb[b] = run; run += v; }
    }
    __syncthreads();
    int i = blockIdx.x * blockDim.x + t;
    if (i >= N_NODES) return;
    int rs = g_scan[i] - g_deg[i] + sb[i / SCAN_B];
    g_row[i] = rs;
    g_cur[i] = rs;
}

__global__ void k_scatter() {
    int i = blockIdx.x * blockDim.x + threadIdx.x;
    if (i >= E_EDGES) return;
    int d = g_dst[i];
    int pos = atomicAdd(&g_cur[d], 1);
    g_csr[pos] = g_src[i];
}

// ---------------- fused softmax + aggregation + finalize ---------------------
// One warp per dst. half2 lane remap: lanes 0-15 even heads / 16-31 odd heads.
__global__ __launch_bounds__(256) void k_agg(const float* __restrict__ bias,
                                             float* __restrict__ out) {
    const int d    = (blockIdx.x * blockDim.x + threadIdx.x) >> 5;
    const int lane = threadIdx.x & 31;
    if (d >= N_NODES) return;

    const int base = g_row[d];
    const int deg  = g_deg[d];
    const int hsel = lane >> 4;          // 0: even heads, 1: odd heads

    float ad_l = 0.0f;
    if (lane < HEADS) ad_l = g_ad[d * HEADS + lane];

    float2 A0 = {0, 0}, A1 = {0, 0}, A2 = {0, 0};
    float s = 0.0f;

    for (int j0 = 0; j0 < deg; j0 += 32) {
        const int nv = min(32, deg - j0);
        int mysrc = 0;
        if (lane < nv) mysrc = g_csr[base + j0 + lane];

        int j = 0;
        for (; j + 1 < nv; j += 2) {
            const int sA = __shfl_sync(0xffffffffu, mysrc, j);
            const int sB = __shfl_sync(0xffffffffu, mysrc, j + 1);
            float wA = 0.0f, wB = 0.0f;
            if (lane < HEADS) {
                float eA = g_as[sA * HEADS + lane] + ad_l;
                float eB = g_as[sB * HEADS + lane] + ad_l;
                eA = eA > 0.0f ? eA : NEG_SLOPE * eA;
                eB = eB > 0.0f ? eB : NEG_SLOPE * eB;
                wA = __expf(eA);
                wB = __expf(eB);
                s += wA + wB;
            }
            const float wA0 = __shfl_sync(0xffffffffu, wA, 0 + hsel);
            const float wA1 = __shfl_sync(0xffffffffu, wA, 2 + hsel);
            const float wA2 = __shfl_sync(0xffffffffu, wA, 4 + hsel);
            const float wB0 = __shfl_sync(0xffffffffu, wB, 0 + hsel);
            const float wB1 = __shfl_sync(0xffffffffu, wB, 2 + hsel);
            const float wB2 = __shfl_sync(0xffffffffu, wB, 4 + hsel);
            const __half2* xA = (const __half2*)&g_xp_h[sA * HC];
            const __half2* xB = (const __half2*)&g_xp_h[sB * HC];
            float2 fA0 = __half22float2(xA[lane]);
            float2 fA1 = __half22float2(xA[32 + lane]);
            float2 fA2 = __half22float2(xA[64 + lane]);
            float2 fB0 = __half22float2(xB[lane]);
            float2 fB1 = __half22float2(xB[32 + lane]);
            float2 fB2 = __half22float2(xB[64 + lane]);
            A0.x += wA0 * fA0.x + wB0 * fB0.x;  A0.y += wA0 * fA0.y + wB0 * fB0.y;
            A1.x += wA1 * fA1.x + wB1 * fB1.x;  A1.y += wA1 * fA1.y + wB1 * fB1.y;
            A2.x += wA2 * fA2.x + wB2 * fB2.x;  A2.y += wA2 * fA2.y + wB2 * fB2.y;
        }
        if (j < nv) {
            const int sA = __shfl_sync(0xffffffffu, mysrc, j);
            float wA = 0.0f;
            if (lane < HEADS) {
                float eA = g_as[sA * HEADS + lane] + ad_l;
                eA = eA > 0.0f ? eA : NEG_SLOPE * eA;
                wA = __expf(eA);
                s += wA;
            }
            const float wA0 = __shfl_sync(0xffffffffu, wA, 0 + hsel);
            const float wA1 = __shfl_sync(0xffffffffu, wA, 2 + hsel);
            const float wA2 = __shfl_sync(0xffffffffu, wA, 4 + hsel);
            const __half2* xA = (const __half2*)&g_xp_h[sA * HC];
            float2 fA0 = __half22float2(xA[lane]);
            float2 fA1 = __half22float2(xA[32 + lane]);
            float2 fA2 = __half22float2(xA[64 + lane]);
            A0.x += wA0 * fA0.x;  A0.y += wA0 * fA0.y;
            A1.x += wA1 * fA1.x;  A1.y += wA1 * fA1.y;
            A2.x += wA2 * fA2.x;  A2.y += wA2 * fA2.y;
        }
    }

    const float s0 = __shfl_sync(0xffffffffu, s, 0 + hsel) + 1e-16f;
    const float s1 = __shfl_sync(0xffffffffu, s, 2 + hsel) + 1e-16f;
    const float s2 = __shfl_sync(0xffffffffu, s, 4 + hsel) + 1e-16f;

    float ox = A0.x / s0 + A1.x / s1 + A2.x / s2;
    float oy = A0.y / s0 + A1.y / s1 + A2.y / s2;
    ox += __shfl_xor_sync(0xffffffffu, ox, 16);
    oy += __shfl_xor_sync(0xffffffffu, oy, 16);

    if (lane < 16) {
        const int c0 = 2 * lane;
        float2 r;
        r.x = selu_f(ox * (1.0f / HEADS) + bias[c0]);
        r.y = selu_f(oy * (1.0f / HEADS) + bias[c0 + 1]);
        ((float2*)&out[d * OUT_F])[lane] = r;
    }
}

// ---------------- launch: fork edge pipeline / proj, join for agg ------------
static cudaStream_t s_edge = nullptr;
static cudaEvent_t  s_evFork = nullptr, s_evJoin = nullptr;

extern "C" void kernel_launch(void* const* d_in, const int* in_sizes, int n_in,
                              void* d_out, int out_size) {
    const float* x       = (const float*)d_in[0];
    const void*  ei      = d_in[1];
    const float* W       = (const float*)d_in[2];
    const float* att_src = (const float*)d_in[3];
    const float* att_dst = (const float*)d_in[4];
    const float* bias    = (const float*)d_in[5];
    float*       out     = (float*)d_out;

    if (s_edge == nullptr) {
        cudaStreamCreateWithFlags(&s_edge, cudaStreamNonBlocking);
        cudaEventCreateWithFlags(&s_evFork, cudaEventDisableTiming);
        cudaEventCreateWithFlags(&s_evJoin, cudaEventDisableTiming);
    }

    // fork: edge pipeline on s_edge, projection on the launch (capture) stream
    cudaEventRecord(s_evFork, 0);
    cudaStreamWaitEvent(s_edge, s_evFork, 0);

    k_prep        <<<(N_NODES + 255) / 256, 256, 0, s_edge>>>(ei);
    k_convert_hist<<<(E_EDGES + 255) / 256, 256, 0, s_edge>>>(ei);
    k_scan1       <<<NB, SCAN_B, 0, s_edge>>>();
    k_scan23      <<<(N_NODES + 255) / 256, 256, 0, s_edge>>>();
    k_scatter     <<<(E_EDGES + 255) / 256, 256, 0, s_edge>>>();
    cudaEventRecord(s_evJoin, s_edge);

    k_proj<<<(N_NODES + PR - 1) / PR, 256>>>(x, W, att_src, att_dst);

    // join, then fused aggregate
    cudaStreamWaitEvent(0, s_evJoin, 0);
    k_agg<<<(N_NODES * 32 + 255) / 256, 256>>>(bias, out);
}